// round 14
// baseline (speedup 1.0000x reference)
#include <cuda_runtime.h>
#include <cuda_bf16.h>
#include <math.h>
#include <stdint.h>

// Problem constants
#define TT 128
#define BB 32
#define VV 10000
#define HH 1024
#define M1 (TT*BB)          // 4096
#define BH (BB*HH)          // 32768

#define RBLK 128
#define RTHR 512

// ---------------- scratch (device globals; no allocation allowed) ----------
__device__ float g_Xz[M1*HH];
__device__ float g_Xr[M1*HH];
__device__ float g_Xh[M1*HH];
__device__ float g_Hs[TT*BB*HH];
__device__ float g_Z[BH];
__device__ float g_G[BH];
__device__ float g_WzT[HH*HH];
__device__ float g_WrT[HH*HH];
__device__ float g_WhT[HH*HH];
__device__ __align__(16) unsigned g_flagArr[RBLK];
// tf32 pre-converted operands
__device__ uint32_t g_inT[M1*VV];
__device__ uint32_t g_Wxz32[VV*HH];
__device__ uint32_t g_Wxr32[VV*HH];
__device__ uint32_t g_Wxh32[VV*HH];
__device__ uint32_t g_Whq32[HH*VV];
__device__ uint32_t g_Hs32[TT*BB*HH];

// ---------------- cp.async helpers -----------------------------------------
__device__ __forceinline__ uint32_t smem_u32(const void* p) {
    return (uint32_t)__cvta_generic_to_shared(p);
}
#define CP_ASYNC16_CG(dst, src) \
    asm volatile("cp.async.cg.shared.global [%0], [%1], 16;\n" :: "r"(dst), "l"(src))
#define CP_ASYNC16_Z(dst, src, sz) \
    asm volatile("cp.async.cg.shared.global [%0], [%1], 16, %2;\n" :: "r"(dst), "l"(src), "r"(sz))
#define CP_COMMIT() asm volatile("cp.async.commit_group;\n" ::: "memory")
#define CP_WAIT(n)  asm volatile("cp.async.wait_group %0;\n" :: "n"(n) : "memory")

__device__ __forceinline__ uint32_t f2tf32(float f) {
    uint32_t u;
    asm("cvt.rna.tf32.f32 %0, %1;" : "=r"(u) : "f"(f));
    return u;
}

// ---------------- tf32 conversion kernels -----------------------------------
__global__ __launch_bounds__(256)
void cvt5(const float* __restrict__ a0, uint32_t* __restrict__ o0, int n0,
          const float* __restrict__ a1, uint32_t* __restrict__ o1, int n1,
          const float* __restrict__ a2, uint32_t* __restrict__ o2, int n2,
          const float* __restrict__ a3, uint32_t* __restrict__ o3, int n3,
          const float* __restrict__ a4, uint32_t* __restrict__ o4, int n4)
{
    const int z = blockIdx.y;
    const float* a = (z == 0) ? a0 : (z == 1) ? a1 : (z == 2) ? a2 : (z == 3) ? a3 : a4;
    uint32_t* o    = (z == 0) ? o0 : (z == 1) ? o1 : (z == 2) ? o2 : (z == 3) ? o3 : o4;
    int n          = (z == 0) ? n0 : (z == 1) ? n1 : (z == 2) ? n2 : (z == 3) ? n3 : n4;
    int i = (blockIdx.x * 256 + threadIdx.x) * 4;
    if (i < n) {
        float4 v = *(const float4*)&a[i];
        uint4 u;
        u.x = f2tf32(v.x); u.y = f2tf32(v.y); u.z = f2tf32(v.z); u.w = f2tf32(v.w);
        *(uint4*)&o[i] = u;
    }
}

__global__ __launch_bounds__(256)
void cvt1(const float* __restrict__ a, uint32_t* __restrict__ o, int n)
{
    int i = (blockIdx.x * 256 + threadIdx.x) * 4;
    if (i < n) {
        float4 v = *(const float4*)&a[i];
        uint4 u;
        u.x = f2tf32(v.x); u.y = f2tf32(v.y); u.z = f2tf32(v.z); u.w = f2tf32(v.w);
        *(uint4*)&o[i] = u;
    }
}

// ============================================================================
// TF32 tensor-core GEMM v3 (R11 winner, reverted verbatim)
// ============================================================================
#define GBM 128
#define GBN 128
#define GBK 16

__device__ __forceinline__ void mma_tf32(float c[4], const uint32_t a[4],
                                         const uint32_t b[2]) {
    asm volatile(
        "mma.sync.aligned.m16n8k8.row.col.f32.tf32.tf32.f32 "
        "{%0,%1,%2,%3}, {%4,%5,%6,%7}, {%8,%9}, {%0,%1,%2,%3};\n"
        : "+f"(c[0]), "+f"(c[1]), "+f"(c[2]), "+f"(c[3])
        : "r"(a[0]), "r"(a[1]), "r"(a[2]), "r"(a[3]), "r"(b[0]), "r"(b[1]));
}

__global__ __launch_bounds__(256)
void tf32_gemm_v3(const uint32_t* __restrict__ A,
                  const uint32_t* __restrict__ B0, const uint32_t* __restrict__ B1,
                  const uint32_t* __restrict__ B2,
                  const float* __restrict__ bias0, const float* __restrict__ bias1,
                  const float* __restrict__ bias2,
                  float* __restrict__ C0, float* __restrict__ C1,
                  float* __restrict__ C2,
                  int M, int N, int K)
{
    __shared__ uint32_t As[2][GBM][GBK + 4];
    __shared__ uint32_t Bs[2][GBK][GBN + 8];

    const int z = blockIdx.z;
    const uint32_t* __restrict__ B = (z == 0) ? B0 : ((z == 1) ? B1 : B2);
    const float* __restrict__ bias = (z == 0) ? bias0 : ((z == 1) ? bias1 : bias2);
    float* __restrict__ C          = (z == 0) ? C0 : ((z == 1) ? C1 : C2);

    const int tid  = threadIdx.x;
    const int wid  = tid >> 5;
    const int lane = tid & 31;
    const int m0 = blockIdx.y * GBM;
    const int n0 = blockIdx.x * GBN;

    const int wm = (wid & 3) * 32;
    const int wn = (wid >> 2) * 64;
    const int g  = lane >> 2;
    const int tg = lane & 3;

    float c[2][8][4];
#pragma unroll
    for (int mt = 0; mt < 2; ++mt)
#pragma unroll
        for (int nt = 0; nt < 8; ++nt)
#pragma unroll
            for (int i = 0; i < 4; ++i) c[mt][nt][i] = 0.f;

    const int arow = tid >> 2, akq = tid & 3;
    const int brow = tid >> 5, bcol4 = tid & 31;

    auto load = [&](int buf, int kc) {
#pragma unroll
        for (int i = 0; i < 2; ++i) {
            int row = arow + i * 64;
            uint32_t d = smem_u32(&As[buf][row][akq * 4]);
            CP_ASYNC16_CG(d, &A[(size_t)(m0 + row) * K + kc + akq * 4]);
        }
#pragma unroll
        for (int i = 0; i < 2; ++i) {
            int krow = brow + i * 8;
            int col = n0 + bcol4 * 4;
            uint32_t d = smem_u32(&Bs[buf][krow][bcol4 * 4]);
            const uint32_t* src = &B[(size_t)(kc + krow) * N + ((col < N) ? col : 0)];
            int sz = (col + 3 < N) ? 16 : 0;
            CP_ASYNC16_Z(d, src, sz);
        }
        CP_COMMIT();
    };

    load(0, 0);
    const int nChunks = K / GBK;
#pragma unroll 1
    for (int cI = 0; cI < nChunks; ++cI) {
        CP_WAIT(0);
        __syncthreads();
        if (cI + 1 < nChunks) load((cI + 1) & 1, (cI + 1) * GBK);

        const int buf = cI & 1;
#pragma unroll
        for (int k8 = 0; k8 < GBK; k8 += 8) {
            uint32_t af[2][4];
#pragma unroll
            for (int mt = 0; mt < 2; ++mt) {
                int ra = wm + mt * 16 + g;
                af[mt][0] = As[buf][ra][k8 + tg];
                af[mt][1] = As[buf][ra + 8][k8 + tg];
                af[mt][2] = As[buf][ra][k8 + tg + 4];
                af[mt][3] = As[buf][ra + 8][k8 + tg + 4];
            }
            uint32_t bf[8][2];
#pragma unroll
            for (int nt = 0; nt < 8; ++nt) {
                int cn = wn + nt * 8 + g;
                bf[nt][0] = Bs[buf][k8 + tg][cn];
                bf[nt][1] = Bs[buf][k8 + tg + 4][cn];
            }
#pragma unroll
            for (int mt = 0; mt < 2; ++mt)
#pragma unroll
                for (int nt = 0; nt < 8; ++nt)
                    mma_tf32(c[mt][nt], af[mt], bf[nt]);
        }
    }

#pragma unroll
    for (int mt = 0; mt < 2; ++mt) {
        int row = m0 + wm + mt * 16 + g;
#pragma unroll
        for (int nt = 0; nt < 8; ++nt) {
            int col = n0 + wn + nt * 8 + tg * 2;
            if (col < N) {
                float2 bb = *(const float2*)&bias[col];
                float2 v0 = make_float2(c[mt][nt][0] + bb.x, c[mt][nt][1] + bb.y);
                float2 v1 = make_float2(c[mt][nt][2] + bb.x, c[mt][nt][3] + bb.y);
                *(float2*)&C[(size_t)row * N + col] = v0;
                *(float2*)&C[(size_t)(row + 8) * N + col] = v1;
            }
        }
    }
}

// ============================================================================
// 1024x1024 transpose
// ============================================================================
__global__ __launch_bounds__(256)
void transpose1024(const float* __restrict__ in, float* __restrict__ out)
{
    __shared__ float t[32][33];
    int x = blockIdx.x * 32 + threadIdx.x;
    int y0 = blockIdx.y * 32 + threadIdx.y;
#pragma unroll
    for (int j = 0; j < 32; j += 8)
        t[threadIdx.y + j][threadIdx.x] = in[(size_t)(y0 + j) * HH + x];
    __syncthreads();
    int xo = blockIdx.y * 32 + threadIdx.x;
    int yo = blockIdx.x * 32 + threadIdx.y;
#pragma unroll
    for (int j = 0; j < 32; j += 8)
        out[(size_t)(yo + j) * HH + xo] = t[threadIdx.x][threadIdx.y + j];
}

// ============================================================================
// Persistent GRU recurrence: R11 body + NEW contention-free flag barrier.
// Arrival = one st.release per block (no atomic serialization); wait = warp 0
// polls all 128 flags (1 ld.v4 per lane) until all >= seq. Monotonic seq.
// ============================================================================
__global__ void bar_init()
{
    int i = threadIdx.x;
    if (i < RBLK) g_flagArr[i] = 0u;
}

__device__ __forceinline__ void grid_bar(unsigned seq)
{
    __threadfence();               // release all prior writes
    __syncthreads();
    if (threadIdx.x < 32) {
        if (threadIdx.x == 0) {
            asm volatile("st.release.gpu.global.u32 [%0], %1;"
                         :: "l"(&g_flagArr[blockIdx.x]), "r"(seq) : "memory");
        }
        const unsigned* p = &g_flagArr[threadIdx.x * 4];
        bool ok;
        do {
            unsigned v0, v1, v2, v3;
            asm volatile("ld.volatile.global.v4.u32 {%0,%1,%2,%3}, [%4];"
                         : "=r"(v0), "=r"(v1), "=r"(v2), "=r"(v3) : "l"(p));
            ok = (v0 >= seq) & (v1 >= seq) & (v2 >= seq) & (v3 >= seq);
        } while (!__all_sync(0xffffffffu, ok));
        __threadfence();           // acquire: order subsequent loads
    }
    __syncthreads();
}

__device__ __forceinline__ float sigf(float x) {
    return 1.f / (1.f + __expf(-x));
}

#define W1_OFF 0
#define W2_OFF 16384
#define HP_OFF 24576
#define HPBUF 4224
#define RED2_OFF 37248
#define POOLF2 (RED2_OFF + 1792)
#define POOL_BYTES (POOLF2 * 4)

#define RKC2 128
#define RST2 132
#define NCHUNK2 (HH / RKC2)

__global__ __launch_bounds__(RTHR, 1)
void gru_persistent(const float* __restrict__ H0,
                    const float* __restrict__ Xz, const float* __restrict__ Xr,
                    const float* __restrict__ Xh,
                    const float* __restrict__ WzT, const float* __restrict__ WrT,
                    const float* __restrict__ WhT,
                    float* __restrict__ Hs, float* __restrict__ Z,
                    float* __restrict__ G)
{
    extern __shared__ float pool[];

    const int tid = threadIdx.x;
    const int blk = blockIdx.x;
    const int w   = tid >> 5;
    const int b   = tid & 31;

    const bool isR = blk >= 64;
    const int c1 = (blk & 63) * 16;
    const int p1c4 = w & 3;
    const int p1kh = w >> 2;
    const float* __restrict__ W1 = isR ? WrT : WzT;

    const int c2 = blk * 8;
    const int p2c4 = w & 1;
    const int p2kh = w >> 1;

    {
#pragma unroll
        for (int i = 0; i < 8; ++i) {
            int s = tid + i * 512;
            int row = s >> 8, q = s & 255;
            *(float4*)&pool[W1_OFF + row * 1024 + q * 4] =
                *(const float4*)&W1[(size_t)(c1 + row) * HH + q * 4];
        }
#pragma unroll
        for (int i = 0; i < 4; ++i) {
            int s = tid + i * 512;
            int row = s >> 8, q = s & 255;
            *(float4*)&pool[W2_OFF + row * 1024 + q * 4] =
                *(const float4*)&WhT[(size_t)(c2 + row) * HH + q * 4];
        }
        __syncthreads();
    }

    const int lrow = tid >> 5;
    const int lq   = tid & 31;

    for (int t = 0; t < TT; ++t) {
        const float* __restrict__ Hprev = (t == 0) ? H0 : (Hs + (size_t)(t - 1) * BH);
        const float* __restrict__ Xz_t = Xz + (size_t)t * BH;
        const float* __restrict__ Xr_t = Xr + (size_t)t * BH;
        const float* __restrict__ Xh_t = Xh + (size_t)t * BH;
        float* __restrict__ Hnew = Hs + (size_t)t * BH;

        // ---------------- phase 1 ----------------
        {
            float4 acc[4];
#pragma unroll
            for (int j = 0; j < 4; ++j) acc[j] = make_float4(0.f, 0.f, 0.f, 0.f);

            auto load1 = [&](int buf, int cI) {
#pragma unroll
                for (int i = 0; i < 2; ++i) {
                    int row = lrow + i * 16;
                    uint32_t d = smem_u32(&pool[HP_OFF + buf * HPBUF + row * RST2 + lq * 4]);
                    CP_ASYNC16_CG(d, &Hprev[row * HH + cI * RKC2 + lq * 4]);
                }
                CP_COMMIT();
            };

            load1(0, 0);
            load1(1, 1);
#pragma unroll 1
            for (int c = 0; c < NCHUNK2; ++c) {
                CP_WAIT(1);
                __syncthreads();
                if (c + 2 < NCHUNK2) load1((c + 2) % 3, c + 2);
                const int buf = c % 3;
                const float* hp = &pool[HP_OFF + buf * HPBUF + b * RST2 + p1kh * 32];
                const float* wp = &pool[W1_OFF + (p1c4 * 4) * 1024 + c * RKC2 + p1kh * 32];
#pragma unroll
                for (int kk = 0; kk < 32; kk += 4) {
                    float4 h = *(const float4*)&hp[kk];
#pragma unroll
                    for (int j = 0; j < 4; ++j) {
                        float4 wj = *(const float4*)&wp[j * 1024 + kk];
                        acc[j].x += h.x * wj.x; acc[j].y += h.y * wj.y;
                        acc[j].z += h.z * wj.z; acc[j].w += h.w * wj.w;
                    }
                }
            }

            float4 s4;
            s4.x = (acc[0].x + acc[0].y) + (acc[0].z + acc[0].w);
            s4.y = (acc[1].x + acc[1].y) + (acc[1].z + acc[1].w);
            s4.z = (acc[2].x + acc[2].y) + (acc[2].z + acc[2].w);
            s4.w = (acc[3].x + acc[3].y) + (acc[3].z + acc[3].w);

            __syncthreads();
            const int grp = b * 4 + p1c4;
            if (p1kh > 0)
                *(float4*)&pool[RED2_OFF + ((p1kh - 1) * 128 + grp) * 4] = s4;
            __syncthreads();
            if (p1kh == 0) {
#pragma unroll
                for (int p = 0; p < 3; ++p) {
                    float4 r = *(const float4*)&pool[RED2_OFF + (p * 128 + grp) * 4];
                    s4.x += r.x; s4.y += r.y; s4.z += r.z; s4.w += r.w;
                }
                const int i0 = b * HH + c1 + p1c4 * 4;
                if (!isR) {
                    float4 x = *(const float4*)&Xz_t[i0];
                    float4 zv;
                    zv.x = sigf(x.x + s4.x); zv.y = sigf(x.y + s4.y);
                    zv.z = sigf(x.z + s4.z); zv.w = sigf(x.w + s4.w);
                    __stcg((float4*)&Z[i0], zv);
                } else {
                    float4 x = *(const float4*)&Xr_t[i0];
                    float4 hpv = __ldcg((const float4*)&Hprev[i0]);
                    float4 gv;
                    gv.x = sigf(x.x + s4.x) * hpv.x;
                    gv.y = sigf(x.y + s4.y) * hpv.y;
                    gv.z = sigf(x.z + s4.z) * hpv.z;
                    gv.w = sigf(x.w + s4.w) * hpv.w;
                    __stcg((float4*)&G[i0], gv);
                }
            }
        }

        grid_bar(2 * t + 1);

        // ---------------- phase 2 ----------------
        {
            float4 acc[4];
#pragma unroll
            for (int j = 0; j < 4; ++j) acc[j] = make_float4(0.f, 0.f, 0.f, 0.f);

            auto load2 = [&](int buf, int cI) {
#pragma unroll
                for (int i = 0; i < 2; ++i) {
                    int row = lrow + i * 16;
                    uint32_t d = smem_u32(&pool[HP_OFF + buf * HPBUF + row * RST2 + lq * 4]);
                    CP_ASYNC16_CG(d, &G[row * HH + cI * RKC2 + lq * 4]);
                }
                CP_COMMIT();
            };

            load2(0, 0);
            load2(1, 1);
#pragma unroll 1
            for (int c = 0; c < NCHUNK2; ++c) {
                CP_WAIT(1);
                __syncthreads();
                if (c + 2 < NCHUNK2) load2((c + 2) % 3, c + 2);
                const int buf = c % 3;
                const float* gp = &pool[HP_OFF + buf * HPBUF + b * RST2 + p2kh * 16];
                const float* wp = &pool[W2_OFF + (p2c4 * 4) * 1024 + c * RKC2 + p2kh * 16];
#pragma unroll
                for (int kk = 0; kk < 16; kk += 4) {
                    float4 g4 = *(const float4*)&gp[kk];
#pragma unroll
                    for (int j = 0; j < 4; ++j) {
                        float4 wj = *(const float4*)&wp[j * 1024 + kk];
                        acc[j].x += g4.x * wj.x; acc[j].y += g4.y * wj.y;
                        acc[j].z += g4.z * wj.z; acc[j].w += g4.w * wj.w;
                    }
                }
            }

            float4 s4;
            s4.x = (acc[0].x + acc[0].y) + (acc[0].z + acc[0].w);
            s4.y = (acc[1].x + acc[1].y) + (acc[1].z + acc[1].w);
            s4.z = (acc[2].x + acc[2].y) + (acc[2].z + acc[2].w);
            s4.w = (acc[3].x + acc[3].y) + (acc[3].z + acc[3].w);

            __syncthreads();
            const int grp = b * 2 + p2c4;
            if (p2kh > 0)
                *(float4*)&pool[RED2_OFF + ((p2kh - 1) * 64 + grp) * 4] = s4;
            __syncthreads();
            if (p2kh == 0) {
#pragma unroll
                for (int p = 0; p < 7; ++p) {
                    float4 r = *(const float4*)&pool[RED2_OFF + (p * 64 + grp) * 4];
                    s4.x += r.x; s4.y += r.y; s4.z += r.z; s4.w += r.w;
                }
                const int i0 = b * HH + c2 + p2c4 * 4;
                float4 x = *(const float4*)&Xh_t[i0];
                float4 zv = __ldcg((const float4*)&Z[i0]);
                float4 hpv = __ldcg((const float4*)&Hprev[i0]);
                float4 o;
                o.x = zv.x * hpv.x + (1.f - zv.x) * tanhf(x.x + s4.x);
                o.y = zv.y * hpv.y + (1.f - zv.y) * tanhf(x.y + s4.y);
                o.z = zv.z * hpv.z + (1.f - zv.z) * tanhf(x.z + s4.z);
                o.w = zv.w * hpv.w + (1.f - zv.w) * tanhf(x.w + s4.w);
                __stcg((float4*)&Hnew[i0], o);
            }
        }

        grid_bar(2 * t + 2);
    }
}

// ---------------- H_last copy ----------------------------------------------
__global__ void copy_hlast(const float* __restrict__ src, float* __restrict__ dst)
{
    int i = blockIdx.x * blockDim.x + threadIdx.x;
    if (i < BH) dst[i] = src[i];
}

// ---------------- launch ----------------------------------------------------
extern "C" void kernel_launch(void* const* d_in, const int* in_sizes, int n_in,
                              void* d_out, int out_size)
{
    const float* inputs = (const float*)d_in[0];
    const float* H0     = (const float*)d_in[1];
    const float* W_xz   = (const float*)d_in[2];
    const float* W_hz   = (const float*)d_in[3];
    const float* b_z    = (const float*)d_in[4];
    const float* W_xr   = (const float*)d_in[5];
    const float* W_hr   = (const float*)d_in[6];
    const float* b_r    = (const float*)d_in[7];
    const float* W_xh   = (const float*)d_in[8];
    const float* W_hh   = (const float*)d_in[9];
    const float* b_h    = (const float*)d_in[10];
    const float* W_hq   = (const float*)d_in[11];
    const float* b_q    = (const float*)d_in[12];

    float* out = (float*)d_out;

    float *Xz, *Xr, *Xh, *Hs, *Zb, *Gb, *WzT, *WrT, *WhT;
    uint32_t *inT, *Wxz32, *Wxr32, *Wxh32, *Whq32, *Hs32;
    cudaGetSymbolAddress((void**)&Xz, g_Xz);
    cudaGetSymbolAddress((void**)&Xr, g_Xr);
    cudaGetSymbolAddress((void**)&Xh, g_Xh);
    cudaGetSymbolAddress((void**)&Hs, g_Hs);
    cudaGetSymbolAddress((void**)&Zb, g_Z);
    cudaGetSymbolAddress((void**)&Gb, g_G);
    cudaGetSymbolAddress((void**)&WzT, g_WzT);
    cudaGetSymbolAddress((void**)&WrT, g_WrT);
    cudaGetSymbolAddress((void**)&WhT, g_WhT);
    cudaGetSymbolAddress((void**)&inT, g_inT);
    cudaGetSymbolAddress((void**)&Wxz32, g_Wxz32);
    cudaGetSymbolAddress((void**)&Wxr32, g_Wxr32);
    cudaGetSymbolAddress((void**)&Wxh32, g_Wxh32);
    cudaGetSymbolAddress((void**)&Whq32, g_Whq32);
    cudaGetSymbolAddress((void**)&Hs32, g_Hs32);

    cudaFuncSetAttribute(gru_persistent,
                         cudaFuncAttributeMaxDynamicSharedMemorySize, POOL_BYTES);

    // 0) pre-convert GEMM operands to tf32, transposes, barrier init
    {
        int maxn = M1 * VV;
        dim3 cg((maxn / 4 + 255) / 256, 5);
        cvt5<<<cg, 256>>>(inputs, inT, M1 * VV,
                          W_xz, Wxz32, VV * HH,
                          W_xr, Wxr32, VV * HH,
                          W_xh, Wxh32, VV * HH,
                          W_hq, Whq32, HH * VV);
        dim3 tg(32, 32), tb(32, 8);
        transpose1024<<<tg, tb>>>(W_hz, WzT);
        transpose1024<<<tg, tb>>>(W_hr, WrT);
        transpose1024<<<tg, tb>>>(W_hh, WhT);
        bar_init<<<1, 256>>>();
    }

    // 1) input projections
    {
        dim3 grid(HH / GBN, M1 / GBM, 3);
        tf32_gemm_v3<<<grid, 256>>>(inT, Wxz32, Wxr32, Wxh32,
                                    b_z, b_r, b_h, Xz, Xr, Xh,
                                    M1, HH, VV);
    }

    // 2) recurrence
    gru_persistent<<<RBLK, RTHR, POOL_BYTES>>>(H0, Xz, Xr, Xh,
                                               WzT, WrT, WhT, Hs, Zb, Gb);

    // 2b) convert Hs to tf32
    cvt1<<<(TT * BB * HH / 4 + 255) / 256, 256>>>(Hs, Hs32, TT * BB * HH);

    // 3) output projection
    {
        dim3 grid((VV + GBN - 1) / GBN, M1 / GBM, 1);
        tf32_gemm_v3<<<grid, 256>>>(Hs32, Whq32, Whq32, Whq32,
                                    b_q, b_q, b_q, out, out, out,
                                    M1, VV, HH);
    }

    // 4) H_last
    if (out_size >= M1 * VV + BH) {
        copy_hlast<<<BH / 256, 256>>>(Hs + (size_t)(TT - 1) * BH,
                                      out + (size_t)M1 * VV);
    }
}

// round 15
// speedup vs baseline: 2.0987x; 2.0987x over previous
#include <cuda_runtime.h>
#include <cuda_bf16.h>
#include <math.h>
#include <stdint.h>

// Problem constants
#define TT 128
#define BB 32
#define VV 10000
#define HH 1024
#define M1 (TT*BB)          // 4096
#define BH (BB*HH)          // 32768

#define RBLK 128
#define RTHR 512

// ---------------- scratch (device globals; no allocation allowed) ----------
__device__ float g_Xz[M1*HH];
__device__ float g_Xr[M1*HH];
__device__ float g_Xh[M1*HH];
__device__ float g_Hs[TT*BB*HH];
__device__ float g_Z[BH];
__device__ float g_G[BH];
__device__ float g_WzT[HH*HH];
__device__ float g_WrT[HH*HH];
__device__ float g_WhT[HH*HH];
__device__ unsigned g_bar[2*TT];
// tf32 pre-converted operands
__device__ uint32_t g_inT[M1*VV];
__device__ uint32_t g_Wxz32[VV*HH];
__device__ uint32_t g_Wxr32[VV*HH];
__device__ uint32_t g_Wxh32[VV*HH];
__device__ uint32_t g_Whq32[HH*VV];
__device__ uint32_t g_Hs32[TT*BB*HH];

// ---------------- cp.async helpers -----------------------------------------
__device__ __forceinline__ uint32_t smem_u32(const void* p) {
    return (uint32_t)__cvta_generic_to_shared(p);
}
#define CP_ASYNC16_CG(dst, src) \
    asm volatile("cp.async.cg.shared.global [%0], [%1], 16;\n" :: "r"(dst), "l"(src))
#define CP_ASYNC16_Z(dst, src, sz) \
    asm volatile("cp.async.cg.shared.global [%0], [%1], 16, %2;\n" :: "r"(dst), "l"(src), "r"(sz))
#define CP_COMMIT() asm volatile("cp.async.commit_group;\n" ::: "memory")
#define CP_WAIT(n)  asm volatile("cp.async.wait_group %0;\n" :: "n"(n) : "memory")

__device__ __forceinline__ uint32_t f2tf32(float f) {
    uint32_t u;
    asm("cvt.rna.tf32.f32 %0, %1;" : "=r"(u) : "f"(f));
    return u;
}

// ---------------- tf32 conversion kernels -----------------------------------
__global__ __launch_bounds__(256)
void cvt5(const float* __restrict__ a0, uint32_t* __restrict__ o0, int n0,
          const float* __restrict__ a1, uint32_t* __restrict__ o1, int n1,
          const float* __restrict__ a2, uint32_t* __restrict__ o2, int n2,
          const float* __restrict__ a3, uint32_t* __restrict__ o3, int n3,
          const float* __restrict__ a4, uint32_t* __restrict__ o4, int n4)
{
    const int z = blockIdx.y;
    const float* a = (z == 0) ? a0 : (z == 1) ? a1 : (z == 2) ? a2 : (z == 3) ? a3 : a4;
    uint32_t* o    = (z == 0) ? o0 : (z == 1) ? o1 : (z == 2) ? o2 : (z == 3) ? o3 : o4;
    int n          = (z == 0) ? n0 : (z == 1) ? n1 : (z == 2) ? n2 : (z == 3) ? n3 : n4;
    int i = (blockIdx.x * 256 + threadIdx.x) * 4;
    if (i < n) {
        float4 v = *(const float4*)&a[i];
        uint4 u;
        u.x = f2tf32(v.x); u.y = f2tf32(v.y); u.z = f2tf32(v.z); u.w = f2tf32(v.w);
        *(uint4*)&o[i] = u;
    }
}

__global__ __launch_bounds__(256)
void cvt1(const float* __restrict__ a, uint32_t* __restrict__ o, int n)
{
    int i = (blockIdx.x * 256 + threadIdx.x) * 4;
    if (i < n) {
        float4 v = *(const float4*)&a[i];
        uint4 u;
        u.x = f2tf32(v.x); u.y = f2tf32(v.y); u.z = f2tf32(v.z); u.w = f2tf32(v.w);
        *(uint4*)&o[i] = u;
    }
}

// ============================================================================
// TF32 tensor-core GEMM v5: R11 layout/inner-loop verbatim, pipeline deepened
// to 3 stages (dynamic smem ring, wait_group 1 -> 2 chunks in flight).
// Per-buffer layout (uint32 words):
//   As: 128 rows x 20 (GBK+4)  = 2560 words, buffers at buf*2560   [0,7680)
//   Bs: 16 rows x 136 (GBN+8)  = 2176 words, at 7680 + buf*2176    [7680,14208)
// ============================================================================
#define GBM 128
#define GBN 128
#define GBK 16
#define GAST 20          // As row stride
#define GBST 136         // Bs row stride
#define GA_BUF 2560
#define GB_OFF 7680
#define GB_BUF 2176
#define GPOOLW 14208
#define GPOOL_BYTES (GPOOLW * 4)   // 56832

__device__ __forceinline__ void mma_tf32(float c[4], const uint32_t a[4],
                                         const uint32_t b[2]) {
    asm volatile(
        "mma.sync.aligned.m16n8k8.row.col.f32.tf32.tf32.f32 "
        "{%0,%1,%2,%3}, {%4,%5,%6,%7}, {%8,%9}, {%0,%1,%2,%3};\n"
        : "+f"(c[0]), "+f"(c[1]), "+f"(c[2]), "+f"(c[3])
        : "r"(a[0]), "r"(a[1]), "r"(a[2]), "r"(a[3]), "r"(b[0]), "r"(b[1]));
}

__global__ __launch_bounds__(256)
void tf32_gemm_v5(const uint32_t* __restrict__ A,
                  const uint32_t* __restrict__ B0, const uint32_t* __restrict__ B1,
                  const uint32_t* __restrict__ B2,
                  const float* __restrict__ bias0, const float* __restrict__ bias1,
                  const float* __restrict__ bias2,
                  float* __restrict__ C0, float* __restrict__ C1,
                  float* __restrict__ C2,
                  int M, int N, int K)
{
    extern __shared__ uint32_t gs[];

    const int z = blockIdx.z;
    const uint32_t* __restrict__ B = (z == 0) ? B0 : ((z == 1) ? B1 : B2);
    const float* __restrict__ bias = (z == 0) ? bias0 : ((z == 1) ? bias1 : bias2);
    float* __restrict__ C          = (z == 0) ? C0 : ((z == 1) ? C1 : C2);

    const int tid  = threadIdx.x;
    const int wid  = tid >> 5;
    const int lane = tid & 31;
    const int m0 = blockIdx.y * GBM;
    const int n0 = blockIdx.x * GBN;

    const int wm = (wid & 3) * 32;
    const int wn = (wid >> 2) * 64;
    const int g  = lane >> 2;
    const int tg = lane & 3;

    float c[2][8][4];
#pragma unroll
    for (int mt = 0; mt < 2; ++mt)
#pragma unroll
        for (int nt = 0; nt < 8; ++nt)
#pragma unroll
            for (int i = 0; i < 4; ++i) c[mt][nt][i] = 0.f;

    const int arow = tid >> 2, akq = tid & 3;
    const int brow = tid >> 5, bcol4 = tid & 31;

    auto load = [&](int buf, int kc) {
#pragma unroll
        for (int i = 0; i < 2; ++i) {
            int row = arow + i * 64;
            uint32_t d = smem_u32(&gs[buf * GA_BUF + row * GAST + akq * 4]);
            CP_ASYNC16_CG(d, &A[(size_t)(m0 + row) * K + kc + akq * 4]);
        }
#pragma unroll
        for (int i = 0; i < 2; ++i) {
            int krow = brow + i * 8;
            int col = n0 + bcol4 * 4;
            uint32_t d = smem_u32(&gs[GB_OFF + buf * GB_BUF + krow * GBST + bcol4 * 4]);
            const uint32_t* src = &B[(size_t)(kc + krow) * N + ((col < N) ? col : 0)];
            int sz = (col + 3 < N) ? 16 : 0;
            CP_ASYNC16_Z(d, src, sz);
        }
        CP_COMMIT();
    };

    const int nChunks = K / GBK;
    load(0, 0);
    if (nChunks > 1) load(1, GBK);

#pragma unroll 1
    for (int cI = 0; cI < nChunks; ++cI) {
        CP_WAIT(1);
        __syncthreads();
        if (cI + 2 < nChunks) load((cI + 2) % 3, (cI + 2) * GBK);

        const uint32_t* Ab = &gs[(cI % 3) * GA_BUF];
        const uint32_t* Bb = &gs[GB_OFF + (cI % 3) * GB_BUF];
#pragma unroll
        for (int k8 = 0; k8 < GBK; k8 += 8) {
            uint32_t af[2][4];
#pragma unroll
            for (int mt = 0; mt < 2; ++mt) {
                int ra = wm + mt * 16 + g;
                af[mt][0] = Ab[ra * GAST + k8 + tg];
                af[mt][1] = Ab[(ra + 8) * GAST + k8 + tg];
                af[mt][2] = Ab[ra * GAST + k8 + tg + 4];
                af[mt][3] = Ab[(ra + 8) * GAST + k8 + tg + 4];
            }
            uint32_t bf[8][2];
#pragma unroll
            for (int nt = 0; nt < 8; ++nt) {
                int cn = wn + nt * 8 + g;
                bf[nt][0] = Bb[(k8 + tg) * GBST + cn];
                bf[nt][1] = Bb[(k8 + tg + 4) * GBST + cn];
            }
#pragma unroll
            for (int mt = 0; mt < 2; ++mt)
#pragma unroll
                for (int nt = 0; nt < 8; ++nt)
                    mma_tf32(c[mt][nt], af[mt], bf[nt]);
        }
    }

#pragma unroll
    for (int mt = 0; mt < 2; ++mt) {
        int row = m0 + wm + mt * 16 + g;
#pragma unroll
        for (int nt = 0; nt < 8; ++nt) {
            int col = n0 + wn + nt * 8 + tg * 2;
            if (col < N) {
                float2 bb = *(const float2*)&bias[col];
                float2 v0 = make_float2(c[mt][nt][0] + bb.x, c[mt][nt][1] + bb.y);
                float2 v1 = make_float2(c[mt][nt][2] + bb.x, c[mt][nt][3] + bb.y);
                *(float2*)&C[(size_t)row * N + col] = v0;
                *(float2*)&C[(size_t)(row + 8) * N + col] = v1;
            }
        }
    }
}

// ============================================================================
// 1024x1024 transpose
// ============================================================================
__global__ __launch_bounds__(256)
void transpose1024(const float* __restrict__ in, float* __restrict__ out)
{
    __shared__ float t[32][33];
    int x = blockIdx.x * 32 + threadIdx.x;
    int y0 = blockIdx.y * 32 + threadIdx.y;
#pragma unroll
    for (int j = 0; j < 32; j += 8)
        t[threadIdx.y + j][threadIdx.x] = in[(size_t)(y0 + j) * HH + x];
    __syncthreads();
    int xo = blockIdx.y * 32 + threadIdx.x;
    int yo = blockIdx.x * 32 + threadIdx.y;
#pragma unroll
    for (int j = 0; j < 32; j += 8)
        out[(size_t)(yo + j) * HH + xo] = t[threadIdx.x][threadIdx.y + j];
}

// ============================================================================
// Persistent GRU recurrence (R11 winner, atomic release/acquire barrier)
// ============================================================================
__global__ void bar_init()
{
    int i = threadIdx.x;
    if (i < 2 * TT) g_bar[i] = 0u;
}

__device__ __forceinline__ void grid_bar(int idx)
{
    __threadfence();
    __syncthreads();
    if (threadIdx.x == 0) {
        unsigned prev;
        asm volatile("atom.add.release.gpu.global.u32 %0, [%1], 1;"
                     : "=r"(prev) : "l"(&g_bar[idx]) : "memory");
        unsigned v;
        do {
            asm volatile("ld.acquire.gpu.global.u32 %0, [%1];"
                         : "=r"(v) : "l"(&g_bar[idx]) : "memory");
        } while (v < RBLK);
        __threadfence();
    }
    __syncthreads();
}

__device__ __forceinline__ float sigf(float x) {
    return 1.f / (1.f + __expf(-x));
}

#define W1_OFF 0
#define W2_OFF 16384
#define HP_OFF 24576
#define HPBUF 4224
#define RED2_OFF 37248
#define POOLF2 (RED2_OFF + 1792)
#define POOL_BYTES (POOLF2 * 4)

#define RKC2 128
#define RST2 132
#define NCHUNK2 (HH / RKC2)

__global__ __launch_bounds__(RTHR, 1)
void gru_persistent(const float* __restrict__ H0,
                    const float* __restrict__ Xz, const float* __restrict__ Xr,
                    const float* __restrict__ Xh,
                    const float* __restrict__ WzT, const float* __restrict__ WrT,
                    const float* __restrict__ WhT,
                    float* __restrict__ Hs, float* __restrict__ Z,
                    float* __restrict__ G)
{
    extern __shared__ float pool[];

    const int tid = threadIdx.x;
    const int blk = blockIdx.x;
    const int w   = tid >> 5;
    const int b   = tid & 31;

    const bool isR = blk >= 64;
    const int c1 = (blk & 63) * 16;
    const int p1c4 = w & 3;
    const int p1kh = w >> 2;
    const float* __restrict__ W1 = isR ? WrT : WzT;

    const int c2 = blk * 8;
    const int p2c4 = w & 1;
    const int p2kh = w >> 1;

    {
#pragma unroll
        for (int i = 0; i < 8; ++i) {
            int s = tid + i * 512;
            int row = s >> 8, q = s & 255;
            *(float4*)&pool[W1_OFF + row * 1024 + q * 4] =
                *(const float4*)&W1[(size_t)(c1 + row) * HH + q * 4];
        }
#pragma unroll
        for (int i = 0; i < 4; ++i) {
            int s = tid + i * 512;
            int row = s >> 8, q = s & 255;
            *(float4*)&pool[W2_OFF + row * 1024 + q * 4] =
                *(const float4*)&WhT[(size_t)(c2 + row) * HH + q * 4];
        }
        __syncthreads();
    }

    const int lrow = tid >> 5;
    const int lq   = tid & 31;

    for (int t = 0; t < TT; ++t) {
        const float* __restrict__ Hprev = (t == 0) ? H0 : (Hs + (size_t)(t - 1) * BH);
        const float* __restrict__ Xz_t = Xz + (size_t)t * BH;
        const float* __restrict__ Xr_t = Xr + (size_t)t * BH;
        const float* __restrict__ Xh_t = Xh + (size_t)t * BH;
        float* __restrict__ Hnew = Hs + (size_t)t * BH;

        // ---------------- phase 1 ----------------
        {
            float4 acc[4];
#pragma unroll
            for (int j = 0; j < 4; ++j) acc[j] = make_float4(0.f, 0.f, 0.f, 0.f);

            auto load1 = [&](int buf, int cI) {
#pragma unroll
                for (int i = 0; i < 2; ++i) {
                    int row = lrow + i * 16;
                    uint32_t d = smem_u32(&pool[HP_OFF + buf * HPBUF + row * RST2 + lq * 4]);
                    CP_ASYNC16_CG(d, &Hprev[row * HH + cI * RKC2 + lq * 4]);
                }
                CP_COMMIT();
            };

            load1(0, 0);
            load1(1, 1);
#pragma unroll 1
            for (int c = 0; c < NCHUNK2; ++c) {
                CP_WAIT(1);
                __syncthreads();
                if (c + 2 < NCHUNK2) load1((c + 2) % 3, c + 2);
                const int buf = c % 3;
                const float* hp = &pool[HP_OFF + buf * HPBUF + b * RST2 + p1kh * 32];
                const float* wp = &pool[W1_OFF + (p1c4 * 4) * 1024 + c * RKC2 + p1kh * 32];
#pragma unroll
                for (int kk = 0; kk < 32; kk += 4) {
                    float4 h = *(const float4*)&hp[kk];
#pragma unroll
                    for (int j = 0; j < 4; ++j) {
                        float4 wj = *(const float4*)&wp[j * 1024 + kk];
                        acc[j].x += h.x * wj.x; acc[j].y += h.y * wj.y;
                        acc[j].z += h.z * wj.z; acc[j].w += h.w * wj.w;
                    }
                }
            }

            float4 s4;
            s4.x = (acc[0].x + acc[0].y) + (acc[0].z + acc[0].w);
            s4.y = (acc[1].x + acc[1].y) + (acc[1].z + acc[1].w);
            s4.z = (acc[2].x + acc[2].y) + (acc[2].z + acc[2].w);
            s4.w = (acc[3].x + acc[3].y) + (acc[3].z + acc[3].w);

            __syncthreads();
            const int grp = b * 4 + p1c4;
            if (p1kh > 0)
                *(float4*)&pool[RED2_OFF + ((p1kh - 1) * 128 + grp) * 4] = s4;
            __syncthreads();
            if (p1kh == 0) {
#pragma unroll
                for (int p = 0; p < 3; ++p) {
                    float4 r = *(const float4*)&pool[RED2_OFF + (p * 128 + grp) * 4];
                    s4.x += r.x; s4.y += r.y; s4.z += r.z; s4.w += r.w;
                }
                const int i0 = b * HH + c1 + p1c4 * 4;
                if (!isR) {
                    float4 x = *(const float4*)&Xz_t[i0];
                    float4 zv;
                    zv.x = sigf(x.x + s4.x); zv.y = sigf(x.y + s4.y);
                    zv.z = sigf(x.z + s4.z); zv.w = sigf(x.w + s4.w);
                    __stcg((float4*)&Z[i0], zv);
                } else {
                    float4 x = *(const float4*)&Xr_t[i0];
                    float4 hpv = __ldcg((const float4*)&Hprev[i0]);
                    float4 gv;
                    gv.x = sigf(x.x + s4.x) * hpv.x;
                    gv.y = sigf(x.y + s4.y) * hpv.y;
                    gv.z = sigf(x.z + s4.z) * hpv.z;
                    gv.w = sigf(x.w + s4.w) * hpv.w;
                    __stcg((float4*)&G[i0], gv);
                }
            }
        }

        grid_bar(2 * t);

        // ---------------- phase 2 ----------------
        {
            float4 acc[4];
#pragma unroll
            for (int j = 0; j < 4; ++j) acc[j] = make_float4(0.f, 0.f, 0.f, 0.f);

            auto load2 = [&](int buf, int cI) {
#pragma unroll
                for (int i = 0; i < 2; ++i) {
                    int row = lrow + i * 16;
                    uint32_t d = smem_u32(&pool[HP_OFF + buf * HPBUF + row * RST2 + lq * 4]);
                    CP_ASYNC16_CG(d, &G[row * HH + cI * RKC2 + lq * 4]);
                }
                CP_COMMIT();
            };

            load2(0, 0);
            load2(1, 1);
#pragma unroll 1
            for (int c = 0; c < NCHUNK2; ++c) {
                CP_WAIT(1);
                __syncthreads();
                if (c + 2 < NCHUNK2) load2((c + 2) % 3, c + 2);
                const int buf = c % 3;
                const float* gp = &pool[HP_OFF + buf * HPBUF + b * RST2 + p2kh * 16];
                const float* wp = &pool[W2_OFF + (p2c4 * 4) * 1024 + c * RKC2 + p2kh * 16];
#pragma unroll
                for (int kk = 0; kk < 16; kk += 4) {
                    float4 g4 = *(const float4*)&gp[kk];
#pragma unroll
                    for (int j = 0; j < 4; ++j) {
                        float4 wj = *(const float4*)&wp[j * 1024 + kk];
                        acc[j].x += g4.x * wj.x; acc[j].y += g4.y * wj.y;
                        acc[j].z += g4.z * wj.z; acc[j].w += g4.w * wj.w;
                    }
                }
            }

            float4 s4;
            s4.x = (acc[0].x + acc[0].y) + (acc[0].z + acc[0].w);
            s4.y = (acc[1].x + acc[1].y) + (acc[1].z + acc[1].w);
            s4.z = (acc[2].x + acc[2].y) + (acc[2].z + acc[2].w);
            s4.w = (acc[3].x + acc[3].y) + (acc[3].z + acc[3].w);

            __syncthreads();
            const int grp = b * 2 + p2c4;
            if (p2kh > 0)
                *(float4*)&pool[RED2_OFF + ((p2kh - 1) * 64 + grp) * 4] = s4;
            __syncthreads();
            if (p2kh == 0) {
#pragma unroll
                for (int p = 0; p < 7; ++p) {
                    float4 r = *(const float4*)&pool[RED2_OFF + (p * 64 + grp) * 4];
                    s4.x += r.x; s4.y += r.y; s4.z += r.z; s4.w += r.w;
                }
                const int i0 = b * HH + c2 + p2c4 * 4;
                float4 x = *(const float4*)&Xh_t[i0];
                float4 zv = __ldcg((const float4*)&Z[i0]);
                float4 hpv = __ldcg((const float4*)&Hprev[i0]);
                float4 o;
                o.x = zv.x * hpv.x + (1.f - zv.x) * tanhf(x.x + s4.x);
                o.y = zv.y * hpv.y + (1.f - zv.y) * tanhf(x.y + s4.y);
                o.z = zv.z * hpv.z + (1.f - zv.z) * tanhf(x.z + s4.z);
                o.w = zv.w * hpv.w + (1.f - zv.w) * tanhf(x.w + s4.w);
                __stcg((float4*)&Hnew[i0], o);
            }
        }

        grid_bar(2 * t + 1);
    }
}

// ---------------- H_last copy ----------------------------------------------
__global__ void copy_hlast(const float* __restrict__ src, float* __restrict__ dst)
{
    int i = blockIdx.x * blockDim.x + threadIdx.x;
    if (i < BH) dst[i] = src[i];
}

// ---------------- launch ----------------------------------------------------
extern "C" void kernel_launch(void* const* d_in, const int* in_sizes, int n_in,
                              void* d_out, int out_size)
{
    const float* inputs = (const float*)d_in[0];
    const float* H0     = (const float*)d_in[1];
    const float* W_xz   = (const float*)d_in[2];
    const float* W_hz   = (const float*)d_in[3];
    const float* b_z    = (const float*)d_in[4];
    const float* W_xr   = (const float*)d_in[5];
    const float* W_hr   = (const float*)d_in[6];
    const float* b_r    = (const float*)d_in[7];
    const float* W_xh   = (const float*)d_in[8];
    const float* W_hh   = (const float*)d_in[9];
    const float* b_h    = (const float*)d_in[10];
    const float* W_hq   = (const float*)d_in[11];
    const float* b_q    = (const float*)d_in[12];

    float* out = (float*)d_out;

    float *Xz, *Xr, *Xh, *Hs, *Zb, *Gb, *WzT, *WrT, *WhT;
    uint32_t *inT, *Wxz32, *Wxr32, *Wxh32, *Whq32, *Hs32;
    cudaGetSymbolAddress((void**)&Xz, g_Xz);
    cudaGetSymbolAddress((void**)&Xr, g_Xr);
    cudaGetSymbolAddress((void**)&Xh, g_Xh);
    cudaGetSymbolAddress((void**)&Hs, g_Hs);
    cudaGetSymbolAddress((void**)&Zb, g_Z);
    cudaGetSymbolAddress((void**)&Gb, g_G);
    cudaGetSymbolAddress((void**)&WzT, g_WzT);
    cudaGetSymbolAddress((void**)&WrT, g_WrT);
    cudaGetSymbolAddress((void**)&WhT, g_WhT);
    cudaGetSymbolAddress((void**)&inT, g_inT);
    cudaGetSymbolAddress((void**)&Wxz32, g_Wxz32);
    cudaGetSymbolAddress((void**)&Wxr32, g_Wxr32);
    cudaGetSymbolAddress((void**)&Wxh32, g_Wxh32);
    cudaGetSymbolAddress((void**)&Whq32, g_Whq32);
    cudaGetSymbolAddress((void**)&Hs32, g_Hs32);

    cudaFuncSetAttribute(gru_persistent,
                         cudaFuncAttributeMaxDynamicSharedMemorySize, POOL_BYTES);
    cudaFuncSetAttribute(tf32_gemm_v5,
                         cudaFuncAttributeMaxDynamicSharedMemorySize, GPOOL_BYTES);

    // 0) pre-convert GEMM operands to tf32, transposes, barrier init
    {
        int maxn = M1 * VV;
        dim3 cg((maxn / 4 + 255) / 256, 5);
        cvt5<<<cg, 256>>>(inputs, inT, M1 * VV,
                          W_xz, Wxz32, VV * HH,
                          W_xr, Wxr32, VV * HH,
                          W_xh, Wxh32, VV * HH,
                          W_hq, Whq32, HH * VV);
        dim3 tg(32, 32), tb(32, 8);
        transpose1024<<<tg, tb>>>(W_hz, WzT);
        transpose1024<<<tg, tb>>>(W_hr, WrT);
        transpose1024<<<tg, tb>>>(W_hh, WhT);
        bar_init<<<1, 256>>>();
    }

    // 1) input projections
    {
        dim3 grid(HH / GBN, M1 / GBM, 3);
        tf32_gemm_v5<<<grid, 256, GPOOL_BYTES>>>(inT, Wxz32, Wxr32, Wxh32,
                                                 b_z, b_r, b_h, Xz, Xr, Xh,
                                                 M1, HH, VV);
    }

    // 2) recurrence
    gru_persistent<<<RBLK, RTHR, POOL_BYTES>>>(H0, Xz, Xr, Xh,
                                               WzT, WrT, WhT, Hs, Zb, Gb);

    // 2b) convert Hs to tf32
    cvt1<<<(TT * BB * HH / 4 + 255) / 256, 256>>>(Hs, Hs32, TT * BB * HH);

    // 3) output projection
    {
        dim3 grid((VV + GBN - 1) / GBN, M1 / GBM, 1);
        tf32_gemm_v5<<<grid, 256, GPOOL_BYTES>>>(Hs32, Whq32, Whq32, Whq32,
                                                 b_q, b_q, b_q, out, out, out,
                                                 M1, VV, HH);
    }

    // 4) H_last
    if (out_size >= M1 * VV + BH) {
        copy_hlast<<<BH / 256, 256>>>(Hs + (size_t)(TT - 1) * BH,
                                      out + (size_t)M1 * VV);
    }
}

// round 16
// speedup vs baseline: 2.1692x; 1.0336x over previous
#include <cuda_runtime.h>
#include <cuda_bf16.h>
#include <math.h>
#include <stdint.h>

// Problem constants
#define TT 128
#define BB 32
#define VV 10000
#define HH 1024
#define M1 (TT*BB)          // 4096
#define BH (BB*HH)          // 32768

#define RBLK 128
#define RTHR 512

// ---------------- scratch (device globals; no allocation allowed) ----------
__device__ float g_Xz[M1*HH];
__device__ float g_Xr[M1*HH];
__device__ float g_Xh[M1*HH];
__device__ float g_Hs[TT*BB*HH];
__device__ float g_Z[BH];
__device__ float g_G[BH];
__device__ float g_WzT[HH*HH];
__device__ float g_WrT[HH*HH];
__device__ float g_WhT[HH*HH];
__device__ unsigned g_bar[2*TT];
// tf32 pre-converted operands
__device__ uint32_t g_inT[M1*VV];
__device__ uint32_t g_Wxz32[VV*HH];
__device__ uint32_t g_Wxr32[VV*HH];
__device__ uint32_t g_Wxh32[VV*HH];
__device__ uint32_t g_Whq32[HH*VV];
__device__ uint32_t g_Hs32[TT*BB*HH];

// ---------------- cp.async helpers -----------------------------------------
__device__ __forceinline__ uint32_t smem_u32(const void* p) {
    return (uint32_t)__cvta_generic_to_shared(p);
}
#define CP_ASYNC16_CG(dst, src) \
    asm volatile("cp.async.cg.shared.global [%0], [%1], 16;\n" :: "r"(dst), "l"(src))
#define CP_ASYNC16_Z(dst, src, sz) \
    asm volatile("cp.async.cg.shared.global [%0], [%1], 16, %2;\n" :: "r"(dst), "l"(src), "r"(sz))
#define CP_COMMIT() asm volatile("cp.async.commit_group;\n" ::: "memory")
#define CP_WAIT(n)  asm volatile("cp.async.wait_group %0;\n" :: "n"(n) : "memory")

__device__ __forceinline__ uint32_t f2tf32(float f) {
    uint32_t u;
    asm("cvt.rna.tf32.f32 %0, %1;" : "=r"(u) : "f"(f));
    return u;
}

// ---------------- tf32 conversion kernels -----------------------------------
__global__ __launch_bounds__(256)
void cvt5(const float* __restrict__ a0, uint32_t* __restrict__ o0, int n0,
          const float* __restrict__ a1, uint32_t* __restrict__ o1, int n1,
          const float* __restrict__ a2, uint32_t* __restrict__ o2, int n2,
          const float* __restrict__ a3, uint32_t* __restrict__ o3, int n3,
          const float* __restrict__ a4, uint32_t* __restrict__ o4, int n4)
{
    const int z = blockIdx.y;
    const float* a = (z == 0) ? a0 : (z == 1) ? a1 : (z == 2) ? a2 : (z == 3) ? a3 : a4;
    uint32_t* o    = (z == 0) ? o0 : (z == 1) ? o1 : (z == 2) ? o2 : (z == 3) ? o3 : o4;
    int n          = (z == 0) ? n0 : (z == 1) ? n1 : (z == 2) ? n2 : (z == 3) ? n3 : n4;
    int i = (blockIdx.x * 256 + threadIdx.x) * 4;
    if (i < n) {
        float4 v = *(const float4*)&a[i];
        uint4 u;
        u.x = f2tf32(v.x); u.y = f2tf32(v.y); u.z = f2tf32(v.z); u.w = f2tf32(v.w);
        *(uint4*)&o[i] = u;
    }
}

// ============================================================================
// TF32 tensor-core GEMM v5 (R14 winner, unchanged): 3-stage cp.async ring.
// ============================================================================
#define GBM 128
#define GBN 128
#define GBK 16
#define GAST 20
#define GBST 136
#define GA_BUF 2560
#define GB_OFF 7680
#define GB_BUF 2176
#define GPOOLW 14208
#define GPOOL_BYTES (GPOOLW * 4)

__device__ __forceinline__ void mma_tf32(float c[4], const uint32_t a[4],
                                         const uint32_t b[2]) {
    asm volatile(
        "mma.sync.aligned.m16n8k8.row.col.f32.tf32.tf32.f32 "
        "{%0,%1,%2,%3}, {%4,%5,%6,%7}, {%8,%9}, {%0,%1,%2,%3};\n"
        : "+f"(c[0]), "+f"(c[1]), "+f"(c[2]), "+f"(c[3])
        : "r"(a[0]), "r"(a[1]), "r"(a[2]), "r"(a[3]), "r"(b[0]), "r"(b[1]));
}

__global__ __launch_bounds__(256)
void tf32_gemm_v5(const uint32_t* __restrict__ A,
                  const uint32_t* __restrict__ B0, const uint32_t* __restrict__ B1,
                  const uint32_t* __restrict__ B2,
                  const float* __restrict__ bias0, const float* __restrict__ bias1,
                  const float* __restrict__ bias2,
                  float* __restrict__ C0, float* __restrict__ C1,
                  float* __restrict__ C2,
                  int M, int N, int K)
{
    extern __shared__ uint32_t gs[];

    const int z = blockIdx.z;
    const uint32_t* __restrict__ B = (z == 0) ? B0 : ((z == 1) ? B1 : B2);
    const float* __restrict__ bias = (z == 0) ? bias0 : ((z == 1) ? bias1 : bias2);
    float* __restrict__ C          = (z == 0) ? C0 : ((z == 1) ? C1 : C2);

    const int tid  = threadIdx.x;
    const int wid  = tid >> 5;
    const int lane = tid & 31;
    const int m0 = blockIdx.y * GBM;
    const int n0 = blockIdx.x * GBN;

    const int wm = (wid & 3) * 32;
    const int wn = (wid >> 2) * 64;
    const int g  = lane >> 2;
    const int tg = lane & 3;

    float c[2][8][4];
#pragma unroll
    for (int mt = 0; mt < 2; ++mt)
#pragma unroll
        for (int nt = 0; nt < 8; ++nt)
#pragma unroll
            for (int i = 0; i < 4; ++i) c[mt][nt][i] = 0.f;

    const int arow = tid >> 2, akq = tid & 3;
    const int brow = tid >> 5, bcol4 = tid & 31;

    auto load = [&](int buf, int kc) {
#pragma unroll
        for (int i = 0; i < 2; ++i) {
            int row = arow + i * 64;
            uint32_t d = smem_u32(&gs[buf * GA_BUF + row * GAST + akq * 4]);
            CP_ASYNC16_CG(d, &A[(size_t)(m0 + row) * K + kc + akq * 4]);
        }
#pragma unroll
        for (int i = 0; i < 2; ++i) {
            int krow = brow + i * 8;
            int col = n0 + bcol4 * 4;
            uint32_t d = smem_u32(&gs[GB_OFF + buf * GB_BUF + krow * GBST + bcol4 * 4]);
            const uint32_t* src = &B[(size_t)(kc + krow) * N + ((col < N) ? col : 0)];
            int sz = (col + 3 < N) ? 16 : 0;
            CP_ASYNC16_Z(d, src, sz);
        }
        CP_COMMIT();
    };

    const int nChunks = K / GBK;
    load(0, 0);
    if (nChunks > 1) load(1, GBK);

#pragma unroll 1
    for (int cI = 0; cI < nChunks; ++cI) {
        CP_WAIT(1);
        __syncthreads();
        if (cI + 2 < nChunks) load((cI + 2) % 3, (cI + 2) * GBK);

        const uint32_t* Ab = &gs[(cI % 3) * GA_BUF];
        const uint32_t* Bb = &gs[GB_OFF + (cI % 3) * GB_BUF];
#pragma unroll
        for (int k8 = 0; k8 < GBK; k8 += 8) {
            uint32_t af[2][4];
#pragma unroll
            for (int mt = 0; mt < 2; ++mt) {
                int ra = wm + mt * 16 + g;
                af[mt][0] = Ab[ra * GAST + k8 + tg];
                af[mt][1] = Ab[(ra + 8) * GAST + k8 + tg];
                af[mt][2] = Ab[ra * GAST + k8 + tg + 4];
                af[mt][3] = Ab[(ra + 8) * GAST + k8 + tg + 4];
            }
            uint32_t bf[8][2];
#pragma unroll
            for (int nt = 0; nt < 8; ++nt) {
                int cn = wn + nt * 8 + g;
                bf[nt][0] = Bb[(k8 + tg) * GBST + cn];
                bf[nt][1] = Bb[(k8 + tg + 4) * GBST + cn];
            }
#pragma unroll
            for (int mt = 0; mt < 2; ++mt)
#pragma unroll
                for (int nt = 0; nt < 8; ++nt)
                    mma_tf32(c[mt][nt], af[mt], bf[nt]);
        }
    }

#pragma unroll
    for (int mt = 0; mt < 2; ++mt) {
        int row = m0 + wm + mt * 16 + g;
#pragma unroll
        for (int nt = 0; nt < 8; ++nt) {
            int col = n0 + wn + nt * 8 + tg * 2;
            if (col < N) {
                float2 bb = *(const float2*)&bias[col];
                float2 v0 = make_float2(c[mt][nt][0] + bb.x, c[mt][nt][1] + bb.y);
                float2 v1 = make_float2(c[mt][nt][2] + bb.x, c[mt][nt][3] + bb.y);
                *(float2*)&C[(size_t)row * N + col] = v0;
                *(float2*)&C[(size_t)(row + 8) * N + col] = v1;
            }
        }
    }
}

// ============================================================================
// 1024x1024 transpose
// ============================================================================
__global__ __launch_bounds__(256)
void transpose1024(const float* __restrict__ in, float* __restrict__ out)
{
    __shared__ float t[32][33];
    int x = blockIdx.x * 32 + threadIdx.x;
    int y0 = blockIdx.y * 32 + threadIdx.y;
#pragma unroll
    for (int j = 0; j < 32; j += 8)
        t[threadIdx.y + j][threadIdx.x] = in[(size_t)(y0 + j) * HH + x];
    __syncthreads();
    int xo = blockIdx.y * 32 + threadIdx.x;
    int yo = blockIdx.x * 32 + threadIdx.y;
#pragma unroll
    for (int j = 0; j < 32; j += 8)
        out[(size_t)(yo + j) * HH + xo] = t[threadIdx.x][threadIdx.y + j];
}

// ============================================================================
// Persistent GRU recurrence: R11 body + epilogue-operand PREFETCH at phase
// start + fused Hs->tf32 conversion in phase2 epilogue.
// ============================================================================
__global__ void bar_init()
{
    int i = threadIdx.x;
    if (i < 2 * TT) g_bar[i] = 0u;
}

__device__ __forceinline__ void grid_bar(int idx)
{
    __threadfence();
    __syncthreads();
    if (threadIdx.x == 0) {
        unsigned prev;
        asm volatile("atom.add.release.gpu.global.u32 %0, [%1], 1;"
                     : "=r"(prev) : "l"(&g_bar[idx]) : "memory");
        unsigned v;
        do {
            asm volatile("ld.acquire.gpu.global.u32 %0, [%1];"
                         : "=r"(v) : "l"(&g_bar[idx]) : "memory");
        } while (v < RBLK);
        __threadfence();
    }
    __syncthreads();
}

__device__ __forceinline__ float sigf(float x) {
    return 1.f / (1.f + __expf(-x));
}

#define W1_OFF 0
#define W2_OFF 16384
#define HP_OFF 24576
#define HPBUF 4224
#define RED2_OFF 37248
#define POOLF2 (RED2_OFF + 1792)
#define POOL_BYTES (POOLF2 * 4)

#define RKC2 128
#define RST2 132
#define NCHUNK2 (HH / RKC2)

__global__ __launch_bounds__(RTHR, 1)
void gru_persistent(const float* __restrict__ H0,
                    const float* __restrict__ Xz, const float* __restrict__ Xr,
                    const float* __restrict__ Xh,
                    const float* __restrict__ WzT, const float* __restrict__ WrT,
                    const float* __restrict__ WhT,
                    float* __restrict__ Hs, float* __restrict__ Z,
                    float* __restrict__ G, uint32_t* __restrict__ Hs32)
{
    extern __shared__ float pool[];

    const int tid = threadIdx.x;
    const int blk = blockIdx.x;
    const int w   = tid >> 5;
    const int b   = tid & 31;

    const bool isR = blk >= 64;
    const int c1 = (blk & 63) * 16;
    const int p1c4 = w & 3;
    const int p1kh = w >> 2;
    const float* __restrict__ W1 = isR ? WrT : WzT;

    const int c2 = blk * 8;
    const int p2c4 = w & 1;
    const int p2kh = w >> 1;

    {
#pragma unroll
        for (int i = 0; i < 8; ++i) {
            int s = tid + i * 512;
            int row = s >> 8, q = s & 255;
            *(float4*)&pool[W1_OFF + row * 1024 + q * 4] =
                *(const float4*)&W1[(size_t)(c1 + row) * HH + q * 4];
        }
#pragma unroll
        for (int i = 0; i < 4; ++i) {
            int s = tid + i * 512;
            int row = s >> 8, q = s & 255;
            *(float4*)&pool[W2_OFF + row * 1024 + q * 4] =
                *(const float4*)&WhT[(size_t)(c2 + row) * HH + q * 4];
        }
        __syncthreads();
    }

    const int lrow = tid >> 5;
    const int lq   = tid & 31;

    const int i1e = b * HH + c1 + p1c4 * 4;   // phase1 epilogue index
    const int i2e = b * HH + c2 + p2c4 * 4;   // phase2 epilogue index

    for (int t = 0; t < TT; ++t) {
        const float* __restrict__ Hprev = (t == 0) ? H0 : (Hs + (size_t)(t - 1) * BH);
        const float* __restrict__ Xz_t = Xz + (size_t)t * BH;
        const float* __restrict__ Xr_t = Xr + (size_t)t * BH;
        const float* __restrict__ Xh_t = Xh + (size_t)t * BH;
        float* __restrict__ Hnew = Hs + (size_t)t * BH;

        // ---------------- phase 1 ----------------
        {
            float4 acc[4];
#pragma unroll
            for (int j = 0; j < 4; ++j) acc[j] = make_float4(0.f, 0.f, 0.f, 0.f);

            auto load1 = [&](int buf, int cI) {
#pragma unroll
                for (int i = 0; i < 2; ++i) {
                    int row = lrow + i * 16;
                    uint32_t d = smem_u32(&pool[HP_OFF + buf * HPBUF + row * RST2 + lq * 4]);
                    CP_ASYNC16_CG(d, &Hprev[row * HH + cI * RKC2 + lq * 4]);
                }
                CP_COMMIT();
            };

            load1(0, 0);
            load1(1, 1);

            // PREFETCH epilogue operands (valid since previous barrier)
            float4 xe = make_float4(0.f, 0.f, 0.f, 0.f);
            float4 hpe = make_float4(0.f, 0.f, 0.f, 0.f);
            if (p1kh == 0) {
                xe = *(const float4*)&(isR ? Xr_t : Xz_t)[i1e];
                if (isR) hpe = __ldcg((const float4*)&Hprev[i1e]);
            }

#pragma unroll 1
            for (int c = 0; c < NCHUNK2; ++c) {
                CP_WAIT(1);
                __syncthreads();
                if (c + 2 < NCHUNK2) load1((c + 2) % 3, c + 2);
                const int buf = c % 3;
                const float* hp = &pool[HP_OFF + buf * HPBUF + b * RST2 + p1kh * 32];
                const float* wp = &pool[W1_OFF + (p1c4 * 4) * 1024 + c * RKC2 + p1kh * 32];
#pragma unroll
                for (int kk = 0; kk < 32; kk += 4) {
                    float4 h = *(const float4*)&hp[kk];
#pragma unroll
                    for (int j = 0; j < 4; ++j) {
                        float4 wj = *(const float4*)&wp[j * 1024 + kk];
                        acc[j].x += h.x * wj.x; acc[j].y += h.y * wj.y;
                        acc[j].z += h.z * wj.z; acc[j].w += h.w * wj.w;
                    }
                }
            }

            float4 s4;
            s4.x = (acc[0].x + acc[0].y) + (acc[0].z + acc[0].w);
            s4.y = (acc[1].x + acc[1].y) + (acc[1].z + acc[1].w);
            s4.z = (acc[2].x + acc[2].y) + (acc[2].z + acc[2].w);
            s4.w = (acc[3].x + acc[3].y) + (acc[3].z + acc[3].w);

            __syncthreads();
            const int grp = b * 4 + p1c4;
            if (p1kh > 0)
                *(float4*)&pool[RED2_OFF + ((p1kh - 1) * 128 + grp) * 4] = s4;
            __syncthreads();
            if (p1kh == 0) {
#pragma unroll
                for (int p = 0; p < 3; ++p) {
                    float4 r = *(const float4*)&pool[RED2_OFF + (p * 128 + grp) * 4];
                    s4.x += r.x; s4.y += r.y; s4.z += r.z; s4.w += r.w;
                }
                if (!isR) {
                    float4 zv;
                    zv.x = sigf(xe.x + s4.x); zv.y = sigf(xe.y + s4.y);
                    zv.z = sigf(xe.z + s4.z); zv.w = sigf(xe.w + s4.w);
                    __stcg((float4*)&Z[i1e], zv);
                } else {
                    float4 gv;
                    gv.x = sigf(xe.x + s4.x) * hpe.x;
                    gv.y = sigf(xe.y + s4.y) * hpe.y;
                    gv.z = sigf(xe.z + s4.z) * hpe.z;
                    gv.w = sigf(xe.w + s4.w) * hpe.w;
                    __stcg((float4*)&G[i1e], gv);
                }
            }
        }

        grid_bar(2 * t);

        // ---------------- phase 2 ----------------
        {
            float4 acc[4];
#pragma unroll
            for (int j = 0; j < 4; ++j) acc[j] = make_float4(0.f, 0.f, 0.f, 0.f);

            auto load2 = [&](int buf, int cI) {
#pragma unroll
                for (int i = 0; i < 2; ++i) {
                    int row = lrow + i * 16;
                    uint32_t d = smem_u32(&pool[HP_OFF + buf * HPBUF + row * RST2 + lq * 4]);
                    CP_ASYNC16_CG(d, &G[row * HH + cI * RKC2 + lq * 4]);
                }
                CP_COMMIT();
            };

            load2(0, 0);
            load2(1, 1);

            // PREFETCH epilogue operands (Z valid after grid_bar above)
            float4 xe = make_float4(0.f, 0.f, 0.f, 0.f);
            float4 zve = make_float4(0.f, 0.f, 0.f, 0.f);
            float4 hpe = make_float4(0.f, 0.f, 0.f, 0.f);
            if (p2kh == 0) {
                xe  = *(const float4*)&Xh_t[i2e];
                zve = __ldcg((const float4*)&Z[i2e]);
                hpe = __ldcg((const float4*)&Hprev[i2e]);
            }

#pragma unroll 1
            for (int c = 0; c < NCHUNK2; ++c) {
                CP_WAIT(1);
                __syncthreads();
                if (c + 2 < NCHUNK2) load2((c + 2) % 3, c + 2);
                const int buf = c % 3;
                const float* gp = &pool[HP_OFF + buf * HPBUF + b * RST2 + p2kh * 16];
                const float* wp = &pool[W2_OFF + (p2c4 * 4) * 1024 + c * RKC2 + p2kh * 16];
#pragma unroll
                for (int kk = 0; kk < 16; kk += 4) {
                    float4 g4 = *(const float4*)&gp[kk];
#pragma unroll
                    for (int j = 0; j < 4; ++j) {
                        float4 wj = *(const float4*)&wp[j * 1024 + kk];
                        acc[j].x += g4.x * wj.x; acc[j].y += g4.y * wj.y;
                        acc[j].z += g4.z * wj.z; acc[j].w += g4.w * wj.w;
                    }
                }
            }

            float4 s4;
            s4.x = (acc[0].x + acc[0].y) + (acc[0].z + acc[0].w);
            s4.y = (acc[1].x + acc[1].y) + (acc[1].z + acc[1].w);
            s4.z = (acc[2].x + acc[2].y) + (acc[2].z + acc[2].w);
            s4.w = (acc[3].x + acc[3].y) + (acc[3].z + acc[3].w);

            __syncthreads();
            const int grp = b * 2 + p2c4;
            if (p2kh > 0)
                *(float4*)&pool[RED2_OFF + ((p2kh - 1) * 64 + grp) * 4] = s4;
            __syncthreads();
            if (p2kh == 0) {
#pragma unroll
                for (int p = 0; p < 7; ++p) {
                    float4 r = *(const float4*)&pool[RED2_OFF + (p * 64 + grp) * 4];
                    s4.x += r.x; s4.y += r.y; s4.z += r.z; s4.w += r.w;
                }
                float4 o;
                o.x = zve.x * hpe.x + (1.f - zve.x) * tanhf(xe.x + s4.x);
                o.y = zve.y * hpe.y + (1.f - zve.y) * tanhf(xe.y + s4.y);
                o.z = zve.z * hpe.z + (1.f - zve.z) * tanhf(xe.z + s4.z);
                o.w = zve.w * hpe.w + (1.f - zve.w) * tanhf(xe.w + s4.w);
                __stcg((float4*)&Hnew[i2e], o);
                // fused tf32 conversion for the output projection
                uint4 u;
                u.x = f2tf32(o.x); u.y = f2tf32(o.y);
                u.z = f2tf32(o.z); u.w = f2tf32(o.w);
                __stcg((uint4*)&Hs32[(size_t)t * BH + i2e], u);
            }
        }

        grid_bar(2 * t + 1);
    }
}

// ---------------- H_last copy ----------------------------------------------
__global__ void copy_hlast(const float* __restrict__ src, float* __restrict__ dst)
{
    int i = blockIdx.x * blockDim.x + threadIdx.x;
    if (i < BH) dst[i] = src[i];
}

// ---------------- launch ----------------------------------------------------
extern "C" void kernel_launch(void* const* d_in, const int* in_sizes, int n_in,
                              void* d_out, int out_size)
{
    const float* inputs = (const float*)d_in[0];
    const float* H0     = (const float*)d_in[1];
    const float* W_xz   = (const float*)d_in[2];
    const float* W_hz   = (const float*)d_in[3];
    const float* b_z    = (const float*)d_in[4];
    const float* W_xr   = (const float*)d_in[5];
    const float* W_hr   = (const float*)d_in[6];
    const float* b_r    = (const float*)d_in[7];
    const float* W_xh   = (const float*)d_in[8];
    const float* W_hh   = (const float*)d_in[9];
    const float* b_h    = (const float*)d_in[10];
    const float* W_hq   = (const float*)d_in[11];
    const float* b_q    = (const float*)d_in[12];

    float* out = (float*)d_out;

    float *Xz, *Xr, *Xh, *Hs, *Zb, *Gb, *WzT, *WrT, *WhT;
    uint32_t *inT, *Wxz32, *Wxr32, *Wxh32, *Whq32, *Hs32;
    cudaGetSymbolAddress((void**)&Xz, g_Xz);
    cudaGetSymbolAddress((void**)&Xr, g_Xr);
    cudaGetSymbolAddress((void**)&Xh, g_Xh);
    cudaGetSymbolAddress((void**)&Hs, g_Hs);
    cudaGetSymbolAddress((void**)&Zb, g_Z);
    cudaGetSymbolAddress((void**)&Gb, g_G);
    cudaGetSymbolAddress((void**)&WzT, g_WzT);
    cudaGetSymbolAddress((void**)&WrT, g_WrT);
    cudaGetSymbolAddress((void**)&WhT, g_WhT);
    cudaGetSymbolAddress((void**)&inT, g_inT);
    cudaGetSymbolAddress((void**)&Wxz32, g_Wxz32);
    cudaGetSymbolAddress((void**)&Wxr32, g_Wxr32);
    cudaGetSymbolAddress((void**)&Wxh32, g_Wxh32);
    cudaGetSymbolAddress((void**)&Whq32, g_Whq32);
    cudaGetSymbolAddress((void**)&Hs32, g_Hs32);

    cudaFuncSetAttribute(gru_persistent,
                         cudaFuncAttributeMaxDynamicSharedMemorySize, POOL_BYTES);
    cudaFuncSetAttribute(tf32_gemm_v5,
                         cudaFuncAttributeMaxDynamicSharedMemorySize, GPOOL_BYTES);

    // 0) pre-convert GEMM operands to tf32, transposes, barrier init
    {
        int maxn = M1 * VV;
        dim3 cg((maxn / 4 + 255) / 256, 5);
        cvt5<<<cg, 256>>>(inputs, inT, M1 * VV,
                          W_xz, Wxz32, VV * HH,
                          W_xr, Wxr32, VV * HH,
                          W_xh, Wxh32, VV * HH,
                          W_hq, Whq32, HH * VV);
        dim3 tg(32, 32), tb(32, 8);
        transpose1024<<<tg, tb>>>(W_hz, WzT);
        transpose1024<<<tg, tb>>>(W_hr, WrT);
        transpose1024<<<tg, tb>>>(W_hh, WhT);
        bar_init<<<1, 256>>>();
    }

    // 1) input projections
    {
        dim3 grid(HH / GBN, M1 / GBM, 3);
        tf32_gemm_v5<<<grid, 256, GPOOL_BYTES>>>(inT, Wxz32, Wxr32, Wxh32,
                                                 b_z, b_r, b_h, Xz, Xr, Xh,
                                                 M1, HH, VV);
    }

    // 2) recurrence (writes Hs and Hs32)
    gru_persistent<<<RBLK, RTHR, POOL_BYTES>>>(H0, Xz, Xr, Xh,
                                               WzT, WrT, WhT, Hs, Zb, Gb, Hs32);

    // 3) output projection
    {
        dim3 grid((VV + GBN - 1) / GBN, M1 / GBM, 1);
        tf32_gemm_v5<<<grid, 256, GPOOL_BYTES>>>(Hs32, Whq32, Whq32, Whq32,
                                                 b_q, b_q, b_q, out, out, out,
                                                 M1, VV, HH);
    }

    // 4) H_last
    if (out_size >= M1 * VV + BH) {
        copy_hlast<<<BH / 256, 256>>>(Hs + (size_t)(TT - 1) * BH,
                                      out + (size_t)M1 * VV);
    }
}